// round 5
// baseline (speedup 1.0000x reference)
#include <cuda_runtime.h>
#include <cstdint>

// Problem constants
#define T_STEPS 512
#define BATCH   64
#define N_IN    512
#define HID     1024

// LSNN parameters
#define DT_TAU_MEM   0.1f
#define DT_TAU_SYN   0.2f
#define DT_TAU_ADAPT 1.25e-6f
#define VTH          1.0f
#define BETA         1.8f

// ---------------------------------------------------------------------------
// Scratch
// ---------------------------------------------------------------------------
__device__ float g_curin[(size_t)T_STEPS * BATCH * HID];   // x @ w_in^T, [T,B,H]
__device__ float g_wrecT[(size_t)HID * HID];               // w_rec^T  [h' , h]
__device__ float g_winT [(size_t)N_IN * HID];              // w_in^T   [k  , h]

// ---------------------------------------------------------------------------
// Packed fp32x2 helpers (per-lane fp32 rounding)
// ---------------------------------------------------------------------------
__device__ __forceinline__ unsigned long long pack_f32x2(float lo, float hi)
{
    unsigned long long r;
    asm("mov.b64 %0, {%1, %2};" : "=l"(r) : "r"(__float_as_uint(lo)), "r"(__float_as_uint(hi)));
    return r;
}
__device__ __forceinline__ void fma_f32x2(unsigned long long& d,
                                          unsigned long long a, unsigned long long b)
{
    asm("fma.rn.f32x2 %0, %1, %2, %0;" : "+l"(d) : "l"(a), "l"(b));
}
__device__ __forceinline__ void add_f32x2(unsigned long long& d, unsigned long long a)
{
    asm("add.rn.f32x2 %0, %0, %1;" : "+l"(d) : "l"(a));
}
__device__ __forceinline__ float2 unpack_f32x2(unsigned long long p)
{
    unsigned int lo, hi;
    asm("mov.b64 {%0, %1}, %2;" : "=r"(lo), "=r"(hi) : "l"(p));
    return make_float2(__uint_as_float(lo), __uint_as_float(hi));
}

// ---------------------------------------------------------------------------
// Tiled transposes writing directly to device symbols
// ---------------------------------------------------------------------------
__device__ __forceinline__ void transpose_impl(const float* __restrict__ in,
                                               float* __restrict__ out,
                                               int rows, int cols)
{
    __shared__ float tile[32][33];
    int c = blockIdx.x * 32 + threadIdx.x;
    int r = blockIdx.y * 32 + threadIdx.y;
#pragma unroll
    for (int j = 0; j < 32; j += 8) {
        if (r + j < rows && c < cols)
            tile[threadIdx.y + j][threadIdx.x] = in[(size_t)(r + j) * cols + c];
    }
    __syncthreads();
    int c2 = blockIdx.y * 32 + threadIdx.x;
    int r2 = blockIdx.x * 32 + threadIdx.y;
#pragma unroll
    for (int j = 0; j < 32; j += 8) {
        if (r2 + j < cols && c2 < rows)
            out[(size_t)(r2 + j) * rows + c2] = tile[threadIdx.x][threadIdx.y + j];
    }
}

__global__ void transpose_wrec_kernel(const float* __restrict__ w_rec)
{
    transpose_impl(w_rec, g_wrecT, HID, HID);
}

__global__ void transpose_win_kernel(const float* __restrict__ w_in)
{
    transpose_impl(w_in, g_winT, HID, N_IN);
}

// ---------------------------------------------------------------------------
// SGEMM (NN) — round-3 version (best measured): 128x128 tile, BK=8, 256 thr,
// 8x8 microtile, double-buffered smem, packed f32x2 FMAs.
// ---------------------------------------------------------------------------
#define BM 128
#define BN 128
#define BK 8
#define TM 8
#define TN 8

__global__ void __launch_bounds__(256, 2)
sgemm_nn_kernel(const float* __restrict__ A)
{
    const int K = N_IN;
    const int N = HID;

    __shared__ float As[2][BK][BM];
    __shared__ float Bs[2][BK][BN];

    const int bm = blockIdx.y * BM;
    const int bn = blockIdx.x * BN;
    const int tid = threadIdx.x;

    const int arow = tid >> 1;
    const int ak   = (tid & 1) * 4;
    const int brow = tid >> 5;
    const int bcol = (tid & 31) * 4;

    const int tx = (tid & 15) * TN;
    const int ty = (tid >> 4) * TM;

    unsigned long long acc2[TM][TN / 2];
#pragma unroll
    for (int m = 0; m < TM; m++)
#pragma unroll
        for (int j = 0; j < TN / 2; j++) acc2[m][j] = 0ull;

    const float* Aptr = A + (size_t)(bm + arow) * K + ak;
    const float* Bptr = g_winT + (size_t)brow * N + bn + bcol;

    float4 av = *(const float4*)Aptr;  Aptr += BK;
    float4 bv = *(const float4*)Bptr;  Bptr += (size_t)BK * N;
    As[0][ak + 0][arow] = av.x;
    As[0][ak + 1][arow] = av.y;
    As[0][ak + 2][arow] = av.z;
    As[0][ak + 3][arow] = av.w;
    *(float4*)&Bs[0][brow][bcol] = bv;
    __syncthreads();

    const int NIT = K / BK;   // 64
    for (int k0 = 0; k0 < NIT; k0++) {
        const int cur = k0 & 1;

        if (k0 + 1 < NIT) {
            av = *(const float4*)Aptr;  Aptr += BK;
            bv = *(const float4*)Bptr;  Bptr += (size_t)BK * N;
        }

#pragma unroll
        for (int kk = 0; kk < BK; kk++) {
            unsigned long long bb[TN / 2];
#pragma unroll
            for (int j = 0; j < TN / 2; j++) {
                float2 t = *(const float2*)&Bs[cur][kk][tx + 2 * j];
                bb[j] = pack_f32x2(t.x, t.y);
            }
#pragma unroll
            for (int m = 0; m < TM; m++) {
                float a = As[cur][kk][ty + m];
                unsigned long long a2 = pack_f32x2(a, a);
#pragma unroll
                for (int j = 0; j < TN / 2; j++)
                    fma_f32x2(acc2[m][j], a2, bb[j]);
            }
        }

        if (k0 + 1 < NIT) {
            const int nxt = cur ^ 1;
            As[nxt][ak + 0][arow] = av.x;
            As[nxt][ak + 1][arow] = av.y;
            As[nxt][ak + 2][arow] = av.z;
            As[nxt][ak + 3][arow] = av.w;
            *(float4*)&Bs[nxt][brow][bcol] = bv;
            __syncthreads();
        }
    }

    float* Cbase = g_curin + (size_t)(bm + ty) * N + bn + tx;
#pragma unroll
    for (int m = 0; m < TM; m++) {
        float* crow = Cbase + (size_t)m * N;
#pragma unroll
        for (int j = 0; j < TN / 2; j += 2) {
            float2 v0 = unpack_f32x2(acc2[m][j]);
            float2 v1 = unpack_f32x2(acc2[m][j + 1]);
            *(float4*)(crow + 2 * j) = make_float4(v0.x, v0.y, v1.x, v1.y);
        }
    }
}

// ---------------------------------------------------------------------------
// LSNN scan: one CTA per batch, 256 threads, 4 consecutive neurons per thread.
// Spike exchange via RAW BALLOT MASKS (no compaction, no prefix scans,
// ONE __syncthreads per step). Gather iterates set bits with __ffs.
// ---------------------------------------------------------------------------
__global__ void __launch_bounds__(256, 1)
lsnn_scan_kernel(float* __restrict__ out)
{
    const int tid   = threadIdx.x;            // 0..255
    const int batch = blockIdx.x;
    const int lane  = tid & 31;
    const int wid   = tid >> 5;               // 0..7
    const int h0    = tid * 4;
    const unsigned FULL = 0xffffffffu;

    // s_mask[buf][w] = {ballot(z0), ballot(z1), ballot(z2), ballot(z3)} of warp w
    __shared__ __align__(16) uint4 s_mask[2][8];

    float v[4]   = {0.f, 0.f, 0.f, 0.f};
    float cur[4] = {0.f, 0.f, 0.f, 0.f};
    float bth[4] = {VTH, VTH, VTH, VTH};
    float zl[4]  = {0.f, 0.f, 0.f, 0.f};
    int buf = 0;

    const float* cin  = g_curin + (size_t)batch * HID + h0;
    float*       outp = out     + (size_t)batch * HID + h0;
    const size_t strideT = (size_t)BATCH * HID;

    if (tid < 16) ((uint4*)s_mask)[tid] = make_uint4(0u, 0u, 0u, 0u);
    __syncthreads();

    float4 gin = __ldg((const float4*)cin);   // t = 0

    for (int t = 0; t < T_STEPS; t++) {
        float4 gin_next = (t + 1 < T_STEPS)
            ? __ldg((const float4*)(cin + (size_t)(t + 1) * strideT))
            : make_float4(0.f, 0.f, 0.f, 0.f);

        // recurrent input: iterate set bits of previous step's ballot masks
        unsigned long long r01 = 0ull, r23 = 0ull;   // packed (rec0,rec1),(rec2,rec3)
        {
            const uint4* mw = s_mask[buf];
            for (int w = 0; w < 8; w++) {
                uint4 mm = mw[w];
                const int nb = w * 128;   // neuron base for this warp's threads
                unsigned m;
                m = mm.x;
                while (m) {
                    int l = __ffs(m) - 1; m &= m - 1;
                    const ulonglong2 ww = *(const ulonglong2*)(g_wrecT + (size_t)(nb + 4 * l + 0) * HID + h0);
                    add_f32x2(r01, ww.x); add_f32x2(r23, ww.y);
                }
                m = mm.y;
                while (m) {
                    int l = __ffs(m) - 1; m &= m - 1;
                    const ulonglong2 ww = *(const ulonglong2*)(g_wrecT + (size_t)(nb + 4 * l + 1) * HID + h0);
                    add_f32x2(r01, ww.x); add_f32x2(r23, ww.y);
                }
                m = mm.z;
                while (m) {
                    int l = __ffs(m) - 1; m &= m - 1;
                    const ulonglong2 ww = *(const ulonglong2*)(g_wrecT + (size_t)(nb + 4 * l + 2) * HID + h0);
                    add_f32x2(r01, ww.x); add_f32x2(r23, ww.y);
                }
                m = mm.w;
                while (m) {
                    int l = __ffs(m) - 1; m &= m - 1;
                    const ulonglong2 ww = *(const ulonglong2*)(g_wrecT + (size_t)(nb + 4 * l + 3) * HID + h0);
                    add_f32x2(r01, ww.x); add_f32x2(r23, ww.y);
                }
            }
        }
        float rec[4];
        {
            float2 a = unpack_f32x2(r01);
            float2 b = unpack_f32x2(r23);
            rec[0] = a.x; rec[1] = a.y; rec[2] = b.x; rec[3] = b.y;
        }
        const float ginv[4] = {gin.x, gin.y, gin.z, gin.w};

        // elementwise dynamics (per neuron, same expression order as reference)
        bool z[4];
        float zf[4];
#pragma unroll
        for (int j = 0; j < 4; j++) {
            float vd   = v[j] + DT_TAU_MEM * (cur[j] - v[j]);
            float idec = cur[j] - DT_TAU_SYN * cur[j];
            float bd   = bth[j] + DT_TAU_ADAPT * (VTH - bth[j]);
            z[j]  = (vd - bd) > 0.0f;
            zf[j] = z[j] ? 1.0f : 0.0f;
            v[j]   = z[j] ? 0.0f : vd;
            bth[j] = bd + (z[j] ? BETA : 0.0f);
            cur[j] = (idec + ginv[j]) + rec[j];
            zl[j]  = zf[j];
        }

        *(float4*)(outp + (size_t)t * strideT) = make_float4(zf[0], zf[1], zf[2], zf[3]);

        // --- publish this step's spike masks (double-buffered, ONE barrier) ---
        unsigned b0 = __ballot_sync(FULL, z[0]);
        unsigned b1 = __ballot_sync(FULL, z[1]);
        unsigned b2 = __ballot_sync(FULL, z[2]);
        unsigned b3 = __ballot_sync(FULL, z[3]);
        const int nbuf = buf ^ 1;
        if (lane == 0) s_mask[nbuf][wid] = make_uint4(b0, b1, b2, b3);
        buf = nbuf;
        __syncthreads();   // masks visible; prior-buffer reads already done

        gin = gin_next;
    }

    // final states: (zf, vf, if, bf) appended after outs [T,B,H]
    const size_t BH = (size_t)BATCH * HID;
    float* fbase = out + (size_t)T_STEPS * BH + (size_t)batch * HID + h0;
    *(float4*)(fbase + 0 * BH) = make_float4(zl[0], zl[1], zl[2], zl[3]);
    *(float4*)(fbase + 1 * BH) = make_float4(v[0], v[1], v[2], v[3]);
    *(float4*)(fbase + 2 * BH) = make_float4(cur[0], cur[1], cur[2], cur[3]);
    *(float4*)(fbase + 3 * BH) = make_float4(bth[0], bth[1], bth[2], bth[3]);
}

// ---------------------------------------------------------------------------
// Launch
// ---------------------------------------------------------------------------
extern "C" void kernel_launch(void* const* d_in, const int* in_sizes, int n_in,
                              void* d_out, int out_size)
{
    const float* x     = (const float*)d_in[0];  // [T, B, N_IN]
    const float* w_in  = (const float*)d_in[1];  // [H, N_IN]
    const float* w_rec = (const float*)d_in[2];  // [H, H]
    float* out = (float*)d_out;

    {
        dim3 blk(32, 8);
        dim3 g2(N_IN / 32, HID / 32);
        transpose_win_kernel<<<g2, blk>>>(w_in);
        dim3 g1(HID / 32, HID / 32);
        transpose_wrec_kernel<<<g1, blk>>>(w_rec);
    }

    {
        dim3 grid(HID / BN, (T_STEPS * BATCH) / BM);
        sgemm_nn_kernel<<<grid, 256>>>(x);
    }

    {
        lsnn_scan_kernel<<<BATCH, 256>>>(out);
    }
}

// round 7
// speedup vs baseline: 1.1467x; 1.1467x over previous
#include <cuda_runtime.h>
#include <cstdint>

// Problem constants
#define T_STEPS 512
#define BATCH   64
#define N_IN    512
#define HID     1024

// LSNN parameters
#define DT_TAU_MEM   0.1f
#define DT_TAU_SYN   0.2f
#define DT_TAU_ADAPT 1.25e-6f
#define VTH          1.0f
#define BETA         1.8f

// ---------------------------------------------------------------------------
// Scratch
// ---------------------------------------------------------------------------
__device__ float g_curin[(size_t)T_STEPS * BATCH * HID];   // x @ w_in^T, [T,B,H]
__device__ float g_wrecT[(size_t)HID * HID];               // w_rec^T  [h' , h]
__device__ float g_winT [(size_t)N_IN * HID];              // w_in^T   [k  , h]

// ---------------------------------------------------------------------------
// Packed fp32x2 helpers (per-lane fp32 rounding)
// ---------------------------------------------------------------------------
__device__ __forceinline__ unsigned long long pack_f32x2(float lo, float hi)
{
    unsigned long long r;
    asm("mov.b64 %0, {%1, %2};" : "=l"(r) : "r"(__float_as_uint(lo)), "r"(__float_as_uint(hi)));
    return r;
}
__device__ __forceinline__ void fma_f32x2(unsigned long long& d,
                                          unsigned long long a, unsigned long long b)
{
    asm("fma.rn.f32x2 %0, %1, %2, %0;" : "+l"(d) : "l"(a), "l"(b));
}
__device__ __forceinline__ void add_f32x2(unsigned long long& d, unsigned long long a)
{
    asm("add.rn.f32x2 %0, %0, %1;" : "+l"(d) : "l"(a));
}
__device__ __forceinline__ float2 unpack_f32x2(unsigned long long p)
{
    unsigned int lo, hi;
    asm("mov.b64 {%0, %1}, %2;" : "=r"(lo), "=r"(hi) : "l"(p));
    return make_float2(__uint_as_float(lo), __uint_as_float(hi));
}

// ---------------------------------------------------------------------------
// Tiled transposes writing directly to device symbols
// ---------------------------------------------------------------------------
__device__ __forceinline__ void transpose_impl(const float* __restrict__ in,
                                               float* __restrict__ out,
                                               int rows, int cols)
{
    __shared__ float tile[32][33];
    int c = blockIdx.x * 32 + threadIdx.x;
    int r = blockIdx.y * 32 + threadIdx.y;
#pragma unroll
    for (int j = 0; j < 32; j += 8) {
        if (r + j < rows && c < cols)
            tile[threadIdx.y + j][threadIdx.x] = in[(size_t)(r + j) * cols + c];
    }
    __syncthreads();
    int c2 = blockIdx.y * 32 + threadIdx.x;
    int r2 = blockIdx.x * 32 + threadIdx.y;
#pragma unroll
    for (int j = 0; j < 32; j += 8) {
        if (r2 + j < cols && c2 < rows)
            out[(size_t)(r2 + j) * rows + c2] = tile[threadIdx.x][threadIdx.y + j];
    }
}

__global__ void transpose_wrec_kernel(const float* __restrict__ w_rec)
{
    transpose_impl(w_rec, g_wrecT, HID, HID);
}

__global__ void transpose_win_kernel(const float* __restrict__ w_in)
{
    transpose_impl(w_in, g_winT, HID, N_IN);
}

// ---------------------------------------------------------------------------
// SGEMM (NN) — round-3 version (best measured): 128x128 tile, BK=8, 256 thr,
// 8x8 microtile, double-buffered smem, packed f32x2 FMAs.
// ---------------------------------------------------------------------------
#define BM 128
#define BN 128
#define BK 8
#define TM 8
#define TN 8

__global__ void __launch_bounds__(256, 2)
sgemm_nn_kernel(const float* __restrict__ A)
{
    const int K = N_IN;
    const int N = HID;

    __shared__ float As[2][BK][BM];
    __shared__ float Bs[2][BK][BN];

    const int bm = blockIdx.y * BM;
    const int bn = blockIdx.x * BN;
    const int tid = threadIdx.x;

    const int arow = tid >> 1;
    const int ak   = (tid & 1) * 4;
    const int brow = tid >> 5;
    const int bcol = (tid & 31) * 4;

    const int tx = (tid & 15) * TN;
    const int ty = (tid >> 4) * TM;

    unsigned long long acc2[TM][TN / 2];
#pragma unroll
    for (int m = 0; m < TM; m++)
#pragma unroll
        for (int j = 0; j < TN / 2; j++) acc2[m][j] = 0ull;

    const float* Aptr = A + (size_t)(bm + arow) * K + ak;
    const float* Bptr = g_winT + (size_t)brow * N + bn + bcol;

    float4 av = *(const float4*)Aptr;  Aptr += BK;
    float4 bv = *(const float4*)Bptr;  Bptr += (size_t)BK * N;
    As[0][ak + 0][arow] = av.x;
    As[0][ak + 1][arow] = av.y;
    As[0][ak + 2][arow] = av.z;
    As[0][ak + 3][arow] = av.w;
    *(float4*)&Bs[0][brow][bcol] = bv;
    __syncthreads();

    const int NIT = K / BK;   // 64
    for (int k0 = 0; k0 < NIT; k0++) {
        const int cur = k0 & 1;

        if (k0 + 1 < NIT) {
            av = *(const float4*)Aptr;  Aptr += BK;
            bv = *(const float4*)Bptr;  Bptr += (size_t)BK * N;
        }

#pragma unroll
        for (int kk = 0; kk < BK; kk++) {
            unsigned long long bb[TN / 2];
#pragma unroll
            for (int j = 0; j < TN / 2; j++) {
                float2 t = *(const float2*)&Bs[cur][kk][tx + 2 * j];
                bb[j] = pack_f32x2(t.x, t.y);
            }
#pragma unroll
            for (int m = 0; m < TM; m++) {
                float a = As[cur][kk][ty + m];
                unsigned long long a2 = pack_f32x2(a, a);
#pragma unroll
                for (int j = 0; j < TN / 2; j++)
                    fma_f32x2(acc2[m][j], a2, bb[j]);
            }
        }

        if (k0 + 1 < NIT) {
            const int nxt = cur ^ 1;
            As[nxt][ak + 0][arow] = av.x;
            As[nxt][ak + 1][arow] = av.y;
            As[nxt][ak + 2][arow] = av.z;
            As[nxt][ak + 3][arow] = av.w;
            *(float4*)&Bs[nxt][brow][bcol] = bv;
            __syncthreads();
        }
    }

    float* Cbase = g_curin + (size_t)(bm + ty) * N + bn + tx;
#pragma unroll
    for (int m = 0; m < TM; m++) {
        float* crow = Cbase + (size_t)m * N;
#pragma unroll
        for (int j = 0; j < TN / 2; j += 2) {
            float2 v0 = unpack_f32x2(acc2[m][j]);
            float2 v1 = unpack_f32x2(acc2[m][j + 1]);
            *(float4*)(crow + 2 * j) = make_float4(v0.x, v0.y, v1.x, v1.y);
        }
    }
}

// ---------------------------------------------------------------------------
// LSNN scan: one CTA per batch, 256 threads, 4 consecutive neurons per thread.
// Round-4 compaction structure + gin prefetch DEPTH 3 (hides DRAM latency).
// ---------------------------------------------------------------------------
#define PF_DEPTH 3

__global__ void __launch_bounds__(256, 1)
lsnn_scan_kernel(float* __restrict__ out)
{
    const int tid   = threadIdx.x;            // 0..255
    const int batch = blockIdx.x;
    const int lane  = tid & 31;
    const int wid   = tid >> 5;               // 0..7
    const int h0    = tid * 4;
    const unsigned FULL = 0xffffffffu;

    __shared__ __align__(16) int s_list[2][HID];
    __shared__ int s_warpcnt[8];

    float v[4]   = {0.f, 0.f, 0.f, 0.f};
    float cur[4] = {0.f, 0.f, 0.f, 0.f};
    float bth[4] = {VTH, VTH, VTH, VTH};
    float zl[4]  = {0.f, 0.f, 0.f, 0.f};
    int cnt = 0;
    int buf = 0;

    const float* cin  = g_curin + (size_t)batch * HID + h0;
    float*       outp = out     + (size_t)batch * HID + h0;
    const size_t strideT = (size_t)BATCH * HID;

    // prefetch pipeline: pf[0] = gin(t), pf[1] = gin(t+1), pf[2] = gin(t+2)
    float4 pf[PF_DEPTH];
#pragma unroll
    for (int j = 0; j < PF_DEPTH; j++)
        pf[j] = __ldg((const float4*)(cin + (size_t)j * strideT));

    for (int t = 0; t < T_STEPS; t++) {
        // issue the deep prefetch FIRST (3 iterations of latency cover)
        float4 pf_new = (t + PF_DEPTH < T_STEPS)
            ? __ldg((const float4*)(cin + (size_t)(t + PF_DEPTH) * strideT))
            : make_float4(0.f, 0.f, 0.f, 0.f);

        float4 gin = pf[0];

        // recurrent input: sum of w_recT rows over previous step's spikes
        unsigned long long r01 = 0ull, r23 = 0ull;
        {
            const int* lst = s_list[buf];
            const int4* lst4 = (const int4*)lst;
            int k = 0;
            for (; k + 4 <= cnt; k += 4) {
                int4 i4 = lst4[k >> 2];
                ulonglong2 w0 = *(const ulonglong2*)(g_wrecT + (size_t)i4.x * HID + h0);
                ulonglong2 w1 = *(const ulonglong2*)(g_wrecT + (size_t)i4.y * HID + h0);
                ulonglong2 w2 = *(const ulonglong2*)(g_wrecT + (size_t)i4.z * HID + h0);
                ulonglong2 w3 = *(const ulonglong2*)(g_wrecT + (size_t)i4.w * HID + h0);
                add_f32x2(r01, w0.x); add_f32x2(r23, w0.y);
                add_f32x2(r01, w1.x); add_f32x2(r23, w1.y);
                add_f32x2(r01, w2.x); add_f32x2(r23, w2.y);
                add_f32x2(r01, w3.x); add_f32x2(r23, w3.y);
            }
            for (; k < cnt; k++) {
                ulonglong2 w = *(const ulonglong2*)(g_wrecT + (size_t)lst[k] * HID + h0);
                add_f32x2(r01, w.x); add_f32x2(r23, w.y);
            }
        }
        float rec[4];
        {
            float2 a = unpack_f32x2(r01);
            float2 b = unpack_f32x2(r23);
            rec[0] = a.x; rec[1] = a.y; rec[2] = b.x; rec[3] = b.y;
        }
        const float ginv[4] = {gin.x, gin.y, gin.z, gin.w};

        // elementwise dynamics
        bool z[4];
        float zf[4];
#pragma unroll
        for (int j = 0; j < 4; j++) {
            float vd   = v[j] + DT_TAU_MEM * (cur[j] - v[j]);
            float idec = cur[j] - DT_TAU_SYN * cur[j];
            float bd   = bth[j] + DT_TAU_ADAPT * (VTH - bth[j]);
            z[j]  = (vd - bd) > 0.0f;
            zf[j] = z[j] ? 1.0f : 0.0f;
            v[j]   = z[j] ? 0.0f : vd;
            bth[j] = bd + (z[j] ? BETA : 0.0f);
            cur[j] = (idec + ginv[j]) + rec[j];
            zl[j]  = zf[j];
        }

        *(float4*)(outp + (size_t)t * strideT) = make_float4(zf[0], zf[1], zf[2], zf[3]);

        // --- rebuild spike list (double-buffered, 2 barriers) ---
        int mycnt = (int)z[0] + (int)z[1] + (int)z[2] + (int)z[3];

        int inc = mycnt;
#pragma unroll
        for (int off = 1; off < 32; off *= 2) {
            int nbr = __shfl_up_sync(FULL, inc, off);
            if (lane >= off) inc += nbr;
        }
        int tex = inc - mycnt;
        if (lane == 31) s_warpcnt[wid] = inc;
        __syncthreads();   // (X) counts visible; old list fully consumed

        int wc = (lane < 8) ? s_warpcnt[lane] : 0;
        int winc = wc;
#pragma unroll
        for (int off = 1; off < 8; off *= 2) {
            int nbr = __shfl_up_sync(FULL, winc, off);
            if (lane >= off) winc += nbr;
        }
        int total = __shfl_sync(FULL, winc, 7);
        int wbase = __shfl_sync(FULL, winc, wid) - __shfl_sync(FULL, wc, wid);

        const int nbuf = buf ^ 1;
        int p = wbase + tex;
        int* nl = s_list[nbuf];
        if (z[0]) nl[p++] = h0 + 0;
        if (z[1]) nl[p++] = h0 + 1;
        if (z[2]) nl[p++] = h0 + 2;
        if (z[3]) nl[p++] = h0 + 3;

        cnt = total;
        buf = nbuf;
        __syncthreads();   // (Y) new list ready

        // rotate prefetch pipeline
        pf[0] = pf[1];
        pf[1] = pf[2];
        pf[2] = pf_new;
    }

    // final states: (zf, vf, if, bf) appended after outs [T,B,H]
    const size_t BH = (size_t)BATCH * HID;
    float* fbase = out + (size_t)T_STEPS * BH + (size_t)batch * HID + h0;
    *(float4*)(fbase + 0 * BH) = make_float4(zl[0], zl[1], zl[2], zl[3]);
    *(float4*)(fbase + 1 * BH) = make_float4(v[0], v[1], v[2], v[3]);
    *(float4*)(fbase + 2 * BH) = make_float4(cur[0], cur[1], cur[2], cur[3]);
    *(float4*)(fbase + 3 * BH) = make_float4(bth[0], bth[1], bth[2], bth[3]);
}

// ---------------------------------------------------------------------------
// Launch
// ---------------------------------------------------------------------------
extern "C" void kernel_launch(void* const* d_in, const int* in_sizes, int n_in,
                              void* d_out, int out_size)
{
    const float* x     = (const float*)d_in[0];  // [T, B, N_IN]
    const float* w_in  = (const float*)d_in[1];  // [H, N_IN]
    const float* w_rec = (const float*)d_in[2];  // [H, H]
    float* out = (float*)d_out;

    {
        dim3 blk(32, 8);
        dim3 g2(N_IN / 32, HID / 32);
        transpose_win_kernel<<<g2, blk>>>(w_in);
        dim3 g1(HID / 32, HID / 32);
        transpose_wrec_kernel<<<g1, blk>>>(w_rec);
    }

    {
        dim3 grid(HID / BN, (T_STEPS * BATCH) / BM);
        sgemm_nn_kernel<<<grid, 256>>>(x);
    }

    {
        lsnn_scan_kernel<<<BATCH, 256>>>(out);
    }
}